// round 16
// baseline (speedup 1.0000x reference)
#include <cuda_runtime.h>
#include <cuda_fp16.h>

#define BATCH 32
#define HW 361
#define H2 38
#define HW2 1444
#define C1IN 512
#define C1OUT 64
#define CR 256
#define C2IN 1280
#define C2OUT 1024
#define CMROWS 600
#define BN_EPS 1e-5f
#define SLOPE 0.1f

// fp16 fragment-packed weights (R9, verified):
#define W2S_U4 (80 * 9 * 64 * 32)
#define W2S_U  (W2S_U4 * 4)
#define WCS_U4 (64 * 40 * 32)
#define WCS_U  (WCS_U4 * 4)

// ---------------- scratch ----------------
__device__ __align__(16) float g_x1r[BATCH * CR * HW];
__device__ __align__(16) float g_pre[BATCH * C2OUT * HW];
__device__ __align__(16) float g_w1t[C1IN * C1OUT];
__device__ __align__(16) uint4 g_w2s4[W2S_U4];
__device__ __align__(16) uint4 g_wcs4[WCS_U4];
__device__ float g_cb[CMROWS];

__device__ __forceinline__ unsigned pack_h2(float a, float b) {
    __half2 h = __floats2half2_rn(a, b);
    return *(unsigned*)&h;
}

// ---------------- prep (R9, verified) ----------------
__global__ void fold_w1(const float* __restrict__ w1, const float* __restrict__ g1,
                        const float* __restrict__ v1) {
    int idx = blockIdx.x * blockDim.x + threadIdx.x;
    if (idx >= C1IN * C1OUT) return;
    int ic = idx >> 6, oc = idx & 63;
    float s = g1[oc] * rsqrtf(v1[oc] + BN_EPS);
    g_w1t[idx] = w1[oc * C1IN + ic] * s;
}

__global__ void fold_w2(const float* __restrict__ w2, const float* __restrict__ g2,
                        const float* __restrict__ v2) {
    int idx = blockIdx.x * blockDim.x + threadIdx.x;
    if (idx >= W2S_U) return;
    int reg = idx & 3, lane = (idx >> 2) & 31;
    int ocb = (idx >> 7) & 63;
    int r2 = idx >> 13;
    int kk = r2 % 9, c = r2 / 9;
    int g = lane >> 2, t = lane & 3;
    int oc = (ocb << 4) + g + ((reg & 1) << 3);
    int ic0 = (c << 4) + 2 * t + ((reg >> 1) << 3);
    float s = g2[oc] * rsqrtf(v2[oc] + BN_EPS);
    float a = w2[(oc * C2IN + ic0) * 9 + kk] * s;
    float b = w2[(oc * C2IN + ic0 + 1) * 9 + kk] * s;
    ((unsigned*)g_w2s4)[idx] = pack_h2(a, b);
}

__global__ void fold_meta(const float* __restrict__ meta) {
    int idx = blockIdx.x * blockDim.x + threadIdx.x;
    if (idx < WCS_U) {
        int reg = idx & 3, lane = (idx >> 2) & 31;
        int cmb = (idx >> 7) % 40;
        int kc = (idx >> 7) / 40;
        int g = lane >> 2, t = lane & 3;
        int cm = (cmb << 4) + g + ((reg & 1) << 3);
        int k0 = (kc << 4) + 2 * t + ((reg >> 1) << 3);
        float a = 0.f, b = 0.f;
        if (cm < CMROWS) {
            a = meta[cm * 1025 + k0];
            b = meta[cm * 1025 + k0 + 1];
        }
        ((unsigned*)g_wcs4)[idx] = pack_h2(a, b);
    } else if (idx < WCS_U + CMROWS) {
        int cm = idx - WCS_U;
        g_cb[cm] = meta[cm * 1025 + 1024];
    }
}

// ---------------- conv1x1 + BN + leaky + reorg (R1, verified) ----------------
__global__ __launch_bounds__(256) void conv1_kernel(
    const float* __restrict__ s5, const float* __restrict__ g1,
    const float* __restrict__ b1, const float* __restrict__ m1,
    const float* __restrict__ v1) {
    __shared__ float in_s[16][64];
    __shared__ float w_s[16][64];
    int b = blockIdx.y;
    int p0 = blockIdx.x * 64;
    int tid = threadIdx.x;
    int tx = tid & 15, ty = tid >> 4;
    float acc[4][4] = {};

    for (int ic0 = 0; ic0 < C1IN; ic0 += 16) {
#pragma unroll
        for (int r = 0; r < 4; r++) {
            int e = tid + r * 256;
            int ic = e >> 6, q = e & 63;
            int pos = p0 + q;
            in_s[ic][q] = (pos < HW2) ? s5[((b * C1IN) + (ic0 + ic)) * HW2 + pos] : 0.f;
            w_s[ic][q] = g_w1t[(ic0 + ic) * 64 + q];
        }
        __syncthreads();
#pragma unroll
        for (int k = 0; k < 16; k++) {
            float4 av = *(const float4*)&in_s[k][tx * 4];
            float4 wv = *(const float4*)&w_s[k][ty * 4];
            float a[4] = {av.x, av.y, av.z, av.w};
            float w[4] = {wv.x, wv.y, wv.z, wv.w};
#pragma unroll
            for (int i = 0; i < 4; i++)
#pragma unroll
                for (int j = 0; j < 4; j++) acc[i][j] += w[i] * a[j];
        }
        __syncthreads();
    }

#pragma unroll
    for (int i = 0; i < 4; i++) {
        int oc = ty * 4 + i;
        float s = g1[oc] * rsqrtf(v1[oc] + BN_EPS);
        float sh = b1[oc] - m1[oc] * s;
#pragma unroll
        for (int j = 0; j < 4; j++) {
            int pos = p0 + tx * 4 + j;
            if (pos < HW2) {
                float v = acc[i][j] + sh;
                v = v > 0.f ? v : SLOPE * v;
                int py = pos / H2, px = pos % H2;
                int oc2 = (py & 1) * 128 + (px & 1) * 64 + oc;
                g_x1r[((b * CR) + oc2) * HW + (py >> 1) * 19 + (px >> 1)] = v;
            }
        }
    }
}

// ---------------- conv3x3, fp16 m16n8k16, 2 batches per block ----------------
// block: 128 oc x 64 pos x 2 batches; weights staged once per chunk, reused 2x.
// grid (6 posTiles, 8 ocTiles, 16 batch-pairs). Dynamic smem: ws4 36.9KB + 2x ins2 5.4KB.
#define INS_STRIDE 168
#define C2_SMEM (9 * 8 * 32 * 16 + 2 * 8 * INS_STRIDE * 4)
__global__ __launch_bounds__(256) void conv2_mma(
    const float* __restrict__ s6, const float* __restrict__ g2,
    const float* __restrict__ b2, const float* __restrict__ m2,
    const float* __restrict__ v2) {
    extern __shared__ __align__(16) char dsm[];
    uint4* ws4 = (uint4*)dsm;                               // [9*8*32]
    unsigned* ins2 = (unsigned*)(dsm + 9 * 8 * 32 * 16);    // [2][8][INS_STRIDE]
    int b0z = blockIdx.z << 1, o0 = blockIdx.y << 7, p0 = blockIdx.x << 6;
    int y0 = p0 / 19 - 1;
    int tid = threadIdx.x, lane = tid & 31, warp = tid >> 5;
    int wo = warp >> 1, wp = warp & 1;
    int g = lane >> 2, t = lane & 3;
    int ocb0 = o0 >> 4;

    int basep[4];
#pragma unroll
    for (int nt = 0; nt < 4; nt++) {
        int pos = p0 + wp * 32 + nt * 8 + g;
        basep[nt] = (pos < HW) ? (pos / 19 - y0) * 21 + pos % 19 : 42;
    }

    float acc[2][2][4][4] = {};   // [batch][mt][nt][reg]

    for (int c = 0; c < 80; c++) {
        // stage input patches for both batches: 2 x 8 ic-pairs x 7 rows x 21 cols
        for (int e = tid; e < 2 * 8 * 147; e += 256) {
            int bb = e / 1176, rem = e - bb * 1176;
            int icp = rem / 147, r = rem - icp * 147;
            int row = r / 21, col = r - row * 21;
            int y = y0 + row, x = col - 1;
            float v0 = 0.f, v1 = 0.f;
            if ((unsigned)y < 19u && (unsigned)x < 19u) {
                int ch = (c << 4) + 2 * icp;
                int b = b0z + bb;
                if (ch < CR) {
                    const float* p = &g_x1r[((b << 8) + ch) * HW + y * 19 + x];
                    v0 = p[0]; v1 = p[HW];
                } else {
                    const float* p = &s6[((b << 10) + (ch - CR)) * HW + y * 19 + x];
                    v0 = p[0]; v1 = p[HW];
                }
            }
            ins2[(bb * 8 + icp) * INS_STRIDE + row * 21 + col] = pack_h2(v0, v1);
        }
        // stage weights once (shared by both batches)
#pragma unroll
        for (int r = 0; r < 9; r++) {
            int f4 = tid + (r << 8);
            int kk = f4 >> 8;
            int rem = f4 & 255;
            int ocb_l = rem >> 5, w4 = rem & 31;
            ws4[f4] = g_w2s4[((c * 9 + kk) * 64 + ocb0 + ocb_l) * 32 + w4];
        }
        __syncthreads();

#pragma unroll
        for (int kk = 0; kk < 9; kk++) {
            const int koff = (kk / 3 - 1) * 21 + (kk % 3);
            uint4 afr[2];
            afr[0] = ws4[(kk << 3) * 32 + (wo * 2 + 0) * 32 + lane];
            afr[1] = ws4[(kk << 3) * 32 + (wo * 2 + 1) * 32 + lane];
#pragma unroll
            for (int bb = 0; bb < 2; bb++) {
#pragma unroll
                for (int nt = 0; nt < 4; nt++) {
                    unsigned bv0 = ins2[(bb * 8 + t) * INS_STRIDE + basep[nt] + koff];
                    unsigned bv1 = ins2[(bb * 8 + t + 4) * INS_STRIDE + basep[nt] + koff];
#pragma unroll
                    for (int mt = 0; mt < 2; mt++) {
                        asm volatile(
                            "mma.sync.aligned.m16n8k16.row.col.f32.f16.f16.f32 "
                            "{%0,%1,%2,%3}, {%4,%5,%6,%7}, {%8,%9}, {%0,%1,%2,%3};\n"
                            : "+f"(acc[bb][mt][nt][0]), "+f"(acc[bb][mt][nt][1]),
                              "+f"(acc[bb][mt][nt][2]), "+f"(acc[bb][mt][nt][3])
                            : "r"(afr[mt].x), "r"(afr[mt].y),
                              "r"(afr[mt].z), "r"(afr[mt].w),
                              "r"(bv0), "r"(bv1));
                    }
                }
            }
        }
        __syncthreads();
    }

#pragma unroll
    for (int mt = 0; mt < 2; mt++) {
#pragma unroll
        for (int rr = 0; rr < 2; rr++) {
            int oc = o0 + wo * 32 + mt * 16 + g + rr * 8;
            float s = g2[oc] * rsqrtf(v2[oc] + BN_EPS);
            float sh = b2[oc] - m2[oc] * s;
#pragma unroll
            for (int bb = 0; bb < 2; bb++) {
                int b = b0z + bb;
#pragma unroll
                for (int nt = 0; nt < 4; nt++) {
                    int pos = p0 + wp * 32 + nt * 8 + 2 * t;
#pragma unroll
                    for (int cc = 0; cc < 2; cc++) {
                        if (pos + cc < HW) {
                            float v = acc[bb][mt][nt][rr * 2 + cc] + sh;
                            v = v > 0.f ? v : SLOPE * v;
                            g_pre[((b << 10) + oc) * HW + pos + cc] = v;
                        }
                    }
                }
            }
        }
    }
}

// ---------------- head GEMM, fp16 m16n8k16 (R9, verified) ----------------
#define PCS_STRIDE 72
__global__ __launch_bounds__(256) void head_mma(float* __restrict__ out) {
    __shared__ __align__(16) uint4 wcs4[2 * 8 * 32];
    __shared__ unsigned pcs2[16][PCS_STRIDE];
    int b = blockIdx.z, cm0 = blockIdx.y << 7, p0 = blockIdx.x << 6;
    int tid = threadIdx.x, lane = tid & 31, warp = tid >> 5;
    int wm = warp >> 1, wp = warp & 1;
    int g = lane >> 2, t = lane & 3;
    int cmb0 = cm0 >> 4;

    float acc[2][4][4] = {};

    for (int c = 0; c < 32; c++) {
        for (int e = tid; e < 1024; e += 256) {
            int kp = e >> 6, q = e & 63;
            int pos = p0 + q;
            float v0 = 0.f, v1 = 0.f;
            if (pos < HW) {
                const float* p = &g_pre[((b << 10) + (c << 5) + 2 * kp) * HW + pos];
                v0 = p[0]; v1 = p[HW];
            }
            pcs2[kp][q] = pack_h2(v0, v1);
        }
#pragma unroll
        for (int r = 0; r < 2; r++) {
            int f4 = tid + (r << 8);
            int kst = f4 >> 8, rem = f4 & 255;
            int cmb_l = rem >> 5, w4 = rem & 31;
            wcs4[f4] = g_wcs4[((c * 2 + kst) * 40 + cmb0 + cmb_l) * 32 + w4];
        }
        __syncthreads();

#pragma unroll
        for (int kst = 0; kst < 2; kst++) {
            uint4 afr[2];
            afr[0] = wcs4[(kst << 3) * 32 + (wm * 2 + 0) * 32 + lane];
            afr[1] = wcs4[(kst << 3) * 32 + (wm * 2 + 1) * 32 + lane];
#pragma unroll
            for (int nt = 0; nt < 4; nt++) {
                int n = wp * 32 + nt * 8 + g;
                unsigned b0 = pcs2[kst * 8 + t][n];
                unsigned b1 = pcs2[kst * 8 + t + 4][n];
#pragma unroll
                for (int mt = 0; mt < 2; mt++) {
                    asm volatile(
                        "mma.sync.aligned.m16n8k16.row.col.f32.f16.f16.f32 "
                        "{%0,%1,%2,%3}, {%4,%5,%6,%7}, {%8,%9}, {%0,%1,%2,%3};\n"
                        : "+f"(acc[mt][nt][0]), "+f"(acc[mt][nt][1]),
                          "+f"(acc[mt][nt][2]), "+f"(acc[mt][nt][3])
                        : "r"(afr[mt].x), "r"(afr[mt].y),
                          "r"(afr[mt].z), "r"(afr[mt].w),
                          "r"(b0), "r"(b1));
                }
            }
        }
        __syncthreads();
    }

#pragma unroll
    for (int mt = 0; mt < 2; mt++) {
#pragma unroll
        for (int rr = 0; rr < 2; rr++) {
            int cm = cm0 + wm * 32 + mt * 16 + g + rr * 8;
            if (cm >= CMROWS) continue;
            float bias = g_cb[cm];
#pragma unroll
            for (int nt = 0; nt < 4; nt++) {
                int pos = p0 + wp * 32 + nt * 8 + 2 * t;
#pragma unroll
                for (int cc = 0; cc < 2; cc++) {
                    if (pos + cc < HW)
                        out[((b * CMROWS) + cm) * HW + pos + cc] =
                            acc[mt][nt][rr * 2 + cc] + bias;
                }
            }
        }
    }
}

// ---------------- launch ----------------
extern "C" void kernel_launch(void* const* d_in, const int* in_sizes, int n_in,
                              void* d_out, int out_size) {
    const float* s6 = (const float*)d_in[0];
    const float* s5 = (const float*)d_in[1];
    const float* w1 = (const float*)d_in[2];
    const float* g1 = (const float*)d_in[3];
    const float* b1 = (const float*)d_in[4];
    const float* m1 = (const float*)d_in[5];
    const float* v1 = (const float*)d_in[6];
    const float* w2 = (const float*)d_in[7];
    const float* g2 = (const float*)d_in[8];
    const float* b2 = (const float*)d_in[9];
    const float* m2 = (const float*)d_in[10];
    const float* v2 = (const float*)d_in[11];
    const float* meta = (const float*)d_in[12];
    float* out = (float*)d_out;

    cudaFuncSetAttribute(conv2_mma, cudaFuncAttributeMaxDynamicSharedMemorySize, C2_SMEM);

    fold_w1<<<(C1IN * C1OUT + 255) / 256, 256>>>(w1, g1, v1);
    fold_w2<<<(W2S_U + 255) / 256, 256>>>(w2, g2, v2);
    fold_meta<<<(WCS_U + CMROWS + 255) / 256, 256>>>(meta);

    conv1_kernel<<<dim3(23, BATCH), 256>>>(s5, g1, b1, m1, v1);
    conv2_mma<<<dim3(6, 8, 16), 256, C2_SMEM>>>(s6, g2, b2, m2, v2);
    head_mma<<<dim3(6, 5, BATCH), 256>>>(out);
}